// round 12
// baseline (speedup 1.0000x reference)
#include <cuda_runtime.h>
#include <cstdint>

#define SS   512
#define OUTN 12
#define CTAS 128
#define NTHR 256
#define XCH  64

typedef uint32_t u32;

__device__ __forceinline__ float tanhax(float x) {
    float r; asm("tanh.approx.f32 %0, %1;" : "=f"(r) : "f"(x)); return r;
}
__device__ __forceinline__ float sig_t(float x) { return fmaf(0.5f, tanhax(0.5f * x), 0.5f); }

__device__ __forceinline__ u32 bf16rn(float x) {      // f32 -> bf16 bits (RN)
    u32 u = __float_as_uint(x);
    u += 0x7fffu + ((u >> 16) & 1u);
    return u >> 16;
}
__device__ __forceinline__ u32 pkbf(float lo, float hi) {   // bf16x2, lo in low half
    return bf16rn(lo) | (bf16rn(hi) << 16);
}
__device__ __forceinline__ float bfres(float v) {     // residual after bf16 rounding
    return v - __uint_as_float(bf16rn(v) << 16);
}
// gate-interleaved column n = 4*u + g  ->  global weight row g*64 + u
__device__ __forceinline__ int grow(int n) { return (n & 3) * 64 + (n >> 2); }

__device__ __forceinline__ void mma16(float d[4], const u32 a[4], u32 b0, u32 b1) {
    asm volatile("mma.sync.aligned.m16n8k16.row.col.f32.bf16.bf16.f32 "
                 "{%0,%1,%2,%3}, {%4,%5,%6,%7}, {%8,%9}, {%0,%1,%2,%3};"
                 : "+f"(d[0]), "+f"(d[1]), "+f"(d[2]), "+f"(d[3])
                 : "r"(a[0]), "r"(a[1]), "r"(a[2]), "r"(a[3]), "r"(b0), "r"(b1));
}

// smem float offsets
#define OF_A0    0        // h0 frags: [2 slot][4 kt][32 lane][4 reg] u32
#define OF_A1    1024     // h1 frags, same shape
#define OF_XS    2048     // [XCH][16]
#define OF_HFIN  3072     // [16 b][64 u]
#define OF_SI0   4096     // [wl][nt8][lane][4]: bias0 n0, n1, wih0 n0, n1
#define OF_SI1   8192     // [wl][nt8][lane][2]: bias1 n0, n1
#define OF_W1H   10240    // Wih1 hi frag: [wl][nt8][kt4][lane][2] u32
#define OF_L1F   18432    // Wih1 lo
#define OF_L0R   26624    // Whh0 lo
#define OF_L2R   34816    // Whh1 lo
#define SMEMF    43008    // 168 KB

#define FR(wl, nt, kt, ln) (((((wl) * 8 + (nt)) * 4 + (kt)) * 32 + (ln)) * 2)

__global__ void __launch_bounds__(NTHR, 1) lstm2_pipe(
    const float* __restrict__ x,
    const float* __restrict__ w_ih0, const float* __restrict__ w_hh0,
    const float* __restrict__ b_ih0, const float* __restrict__ b_hh0,
    const float* __restrict__ w_ih1, const float* __restrict__ w_hh1,
    const float* __restrict__ b_ih1, const float* __restrict__ b_hh1,
    const float* __restrict__ fc_w, const float* __restrict__ fc_b,
    float* __restrict__ out)
{
    extern __shared__ float sm[];
    u32*   A0   = (u32*)(sm + OF_A0);
    u32*   A1   = (u32*)(sm + OF_A1);
    float* xs   = sm + OF_XS;
    float* hfin = sm + OF_HFIN;
    float* si0  = sm + OF_SI0;
    float* si1  = sm + OF_SI1;
    u32*   w1h  = (u32*)(sm + OF_W1H);
    u32*   l1f  = (u32*)(sm + OF_L1F);
    u32*   l0r  = (u32*)(sm + OF_L0R);
    u32*   l2r  = (u32*)(sm + OF_L2R);

    const int tid  = threadIdx.x;
    const int lane = tid & 31;
    const int w    = tid >> 5;
    const int grp  = w >> 2;            // 0: layer0 warps, 1: layer1 warps
    const int wl   = w & 3;             // warp-in-group; owns cols [64wl, 64wl+64)
    const int g    = lane >> 2;
    const int tg   = lane & 3;
    const int evn  = (tg & 1) == 0;
    const int rr   = g + 8 * (tg & 1);  // batch row this lane cells
    const int b0g  = blockIdx.x * 16;

    // ---------------- one-time staging ----------------
    for (int e = tid; e < 2048; e += NTHR) sm[e] = 0.f;   // zero A0+A1 (h(-1)=0)

    // Unified hi-frag array: Whh0 for grp0, Whh1 for grp1. Residuals -> smem.
    u32 rhh[8][4][2];
    const float* Whh = grp ? w_hh1 : w_hh0;
    u32* lres = grp ? l2r : l0r;
#pragma unroll
    for (int nt = 0; nt < 8; nt++) {
        const int n  = wl * 64 + nt * 8 + g;
        const int gr = grow(n);
#pragma unroll
        for (int kt = 0; kt < 4; kt++) {
            const int k0 = 16 * kt + 2 * tg;
            const int fo = FR(wl, nt, kt, lane);
            float v00 = Whh[gr * 64 + k0],     v01 = Whh[gr * 64 + k0 + 1];
            float v10 = Whh[gr * 64 + k0 + 8], v11 = Whh[gr * 64 + k0 + 9];
            rhh[nt][kt][0] = pkbf(v00, v01);
            rhh[nt][kt][1] = pkbf(v10, v11);
            lres[fo + 0] = pkbf(bfres(v00), bfres(v01));
            lres[fo + 1] = pkbf(bfres(v10), bfres(v11));
            if (grp) {   // Wih1 hi + lo -> smem
                v00 = w_ih1[gr * 64 + k0];     v01 = w_ih1[gr * 64 + k0 + 1];
                v10 = w_ih1[gr * 64 + k0 + 8]; v11 = w_ih1[gr * 64 + k0 + 9];
                w1h[fo + 0] = pkbf(v00, v01);
                w1h[fo + 1] = pkbf(v10, v11);
                l1f[fo + 0] = pkbf(bfres(v00), bfres(v01));
                l1f[fo + 1] = pkbf(bfres(v10), bfres(v11));
            }
        }
        // bias / input tables
        const int n0 = wl * 64 + nt * 8 + 2 * tg, n1 = n0 + 1;
        const int g0 = grow(n0), g1 = grow(n1);
        if (!grp) {
            float* p0 = si0 + (((wl * 8 + nt) * 32) + lane) * 4;
            p0[0] = b_ih0[g0] + b_hh0[g0];
            p0[1] = b_ih0[g1] + b_hh0[g1];
            p0[2] = w_ih0[g0];               // INPUT_SIZE == 1
            p0[3] = w_ih0[g1];
        } else {
            float* p1 = si1 + (((wl * 8 + nt) * 32) + lane) * 2;
            p1[0] = b_ih1[g0] + b_hh1[g0];
            p1[1] = b_ih1[g1] + b_hh1[g1];
        }
    }

    // publish slots: unit-pair kpn = 8*wl + nt  ->  kt_=wl, kp8=nt
    int pub_idx[8];
#pragma unroll
    for (int nt = 0; nt < 8; nt++) {
        const int lane_ = (rr & 7) * 4 + (nt & 3);
        const int reg = (nt >= 4 ? 2 : 0) + (rr >= 8 ? 1 : 0);
        pub_idx[nt] = ((wl * 32 + lane_) * 4) + reg;
    }

    float c[8], hv[8];
#pragma unroll
    for (int i = 0; i < 8; i++) { c[i] = 0.f; hv[i] = 0.f; }
    __syncthreads();

    // ---------------- pipelined recurrence: 513 iterations ----------------
    for (int k = 0; k <= SS; k++) {
        if (k < SS && (k & (XCH - 1)) == 0) {     // refill x chunk [k, k+XCH)
            __syncthreads();
            for (int e = tid; e < 16 * XCH; e += NTHR) {
                int tc = e & (XCH - 1), b = e >> 6;
                xs[tc * 16 + b] = x[(size_t)(b0g + b) * SS + k + tc];
            }
            __syncthreads();
        }

        if (!grp) {
            // ===== layer 0, step k: h0[k] =====
            if (k < SS) {
                const u32* Ar = A0 + ((k - 1) & 1) * 512;   // h0[k-1]
                u32* Aw = A0 + (k & 1) * 512;
                const int tloc = k & (XCH - 1);
                const float xg  = xs[tloc * 16 + g];
                const float xg8 = xs[tloc * 16 + g + 8];

                float D[8][4];
#pragma unroll
                for (int nt = 0; nt < 8; nt++) {
                    float4 ini = *(const float4*)(si0 + (((wl * 8 + nt) * 32) + lane) * 4);
                    D[nt][0] = fmaf(ini.z, xg,  ini.x);
                    D[nt][1] = fmaf(ini.w, xg,  ini.y);
                    D[nt][2] = fmaf(ini.z, xg8, ini.x);
                    D[nt][3] = fmaf(ini.w, xg8, ini.y);
                }
#pragma unroll
                for (int kt = 0; kt < 4; kt++) {
                    u32 a[4];
                    *(uint4*)a = *(const uint4*)(Ar + (kt * 32 + lane) * 4);
#pragma unroll
                    for (int nt = 0; nt < 8; nt++)
                        mma16(D[nt], a, rhh[nt][kt][0], rhh[nt][kt][1]);
#pragma unroll
                    for (int nt = 0; nt < 8; nt++) {
                        uint2 lp = *(const uint2*)(l0r + FR(wl, nt, kt, lane));
                        mma16(D[nt], a, lp.x, lp.y);
                    }
                }
                // cell 0
#pragma unroll
                for (int nt = 0; nt < 8; nt++) {
                    float s0 = evn ? D[nt][2] : D[nt][0];
                    float s1 = evn ? D[nt][3] : D[nt][1];
                    float r0 = __shfl_xor_sync(0xffffffffu, s0, 1);
                    float r1 = __shfl_xor_sync(0xffffffffu, s1, 1);
                    float iv = evn ? D[nt][0] : r0;
                    float fv = evn ? D[nt][1] : r1;
                    float gv = evn ? r0       : D[nt][2];
                    float ov = evn ? r1       : D[nt][3];
                    float cc = fmaf(sig_t(fv), c[nt], sig_t(iv) * tanhax(gv));
                    c[nt] = cc;
                    hv[nt] = sig_t(ov) * tanhax(cc);
                }
#pragma unroll
                for (int nt = 0; nt < 8; nt++) {
                    float oth = __shfl_xor_sync(0xffffffffu, hv[nt], 2);
                    if (tg < 2) Aw[pub_idx[nt]] = pkbf(hv[nt], oth);
                }
            }
        } else {
            // ===== layer 1, step k-1: h1[k-1] =====
            if (k >= 1) {
                const u32* A0r = A0 + ((k - 1) & 1) * 512;  // h0[k-1]
                const u32* A1r = A1 + (k & 1) * 512;        // h1[k-2]
                u32* A1w = A1 + ((k & 1) ^ 1) * 512;

                float D[8][4];
#pragma unroll
                for (int nt = 0; nt < 8; nt++) {
                    float2 bi = *(const float2*)(si1 + (((wl * 8 + nt) * 32) + lane) * 2);
                    D[nt][0] = bi.x; D[nt][1] = bi.y;
                    D[nt][2] = bi.x; D[nt][3] = bi.y;
                }
#pragma unroll
                for (int kt = 0; kt < 4; kt++) {
                    u32 a[4], b[4];
                    *(uint4*)a = *(const uint4*)(A0r + (kt * 32 + lane) * 4);
                    *(uint4*)b = *(const uint4*)(A1r + (kt * 32 + lane) * 4);
#pragma unroll
                    for (int nt = 0; nt < 8; nt++)
                        mma16(D[nt], b, rhh[nt][kt][0], rhh[nt][kt][1]);
#pragma unroll
                    for (int nt = 0; nt < 8; nt++) {
                        uint2 hp = *(const uint2*)(w1h + FR(wl, nt, kt, lane));
                        mma16(D[nt], a, hp.x, hp.y);
                    }
#pragma unroll
                    for (int nt = 0; nt < 8; nt++) {
                        uint2 lp = *(const uint2*)(l2r + FR(wl, nt, kt, lane));
                        mma16(D[nt], b, lp.x, lp.y);
                    }
#pragma unroll
                    for (int nt = 0; nt < 8; nt++) {
                        uint2 lp = *(const uint2*)(l1f + FR(wl, nt, kt, lane));
                        mma16(D[nt], a, lp.x, lp.y);
                    }
                }
                // cell 1
#pragma unroll
                for (int nt = 0; nt < 8; nt++) {
                    float s0 = evn ? D[nt][2] : D[nt][0];
                    float s1 = evn ? D[nt][3] : D[nt][1];
                    float r0 = __shfl_xor_sync(0xffffffffu, s0, 1);
                    float r1 = __shfl_xor_sync(0xffffffffu, s1, 1);
                    float iv = evn ? D[nt][0] : r0;
                    float fv = evn ? D[nt][1] : r1;
                    float gv = evn ? r0       : D[nt][2];
                    float ov = evn ? r1       : D[nt][3];
                    float cc = fmaf(sig_t(fv), c[nt], sig_t(iv) * tanhax(gv));
                    c[nt] = cc;
                    hv[nt] = sig_t(ov) * tanhax(cc);
                }
#pragma unroll
                for (int nt = 0; nt < 8; nt++) {
                    float oth = __shfl_xor_sync(0xffffffffu, hv[nt], 2);
                    if (tg < 2) A1w[pub_idx[nt]] = pkbf(hv[nt], oth);
                }
            }
        }
        __syncthreads();
    }

    // ---------------- epilogue ----------------
    // L1 warps hold h1[SS-1] in hv (computed at iter k = SS)
    if (grp) {
#pragma unroll
        for (int nt = 0; nt < 8; nt++)
            hfin[rr * 64 + (wl * 16 + 2 * nt + (tg >> 1))] = hv[nt];
    }
    __syncthreads();

    for (int idx = tid; idx < 16 * OUTN; idx += NTHR) {
        int b = idx / OUTN, o = idx - b * OUTN;
        float s = fc_b[o];
#pragma unroll 16
        for (int uu = 0; uu < 64; uu++)
            s += hfin[b * 64 + uu] * fc_w[o * 64 + uu];
        out[(size_t)(b0g + b) * OUTN + o] = s;
    }
}

extern "C" void kernel_launch(void* const* d_in, const int* in_sizes, int n_in,
                              void* d_out, int out_size) {
    (void)in_sizes; (void)n_in; (void)out_size;
    const float* x     = (const float*)d_in[0];
    const float* w_ih0 = (const float*)d_in[1];
    const float* w_hh0 = (const float*)d_in[2];
    const float* b_ih0 = (const float*)d_in[3];
    const float* b_hh0 = (const float*)d_in[4];
    const float* w_ih1 = (const float*)d_in[5];
    const float* w_hh1 = (const float*)d_in[6];
    const float* b_ih1 = (const float*)d_in[7];
    const float* b_hh1 = (const float*)d_in[8];
    const float* fc_w  = (const float*)d_in[9];
    const float* fc_b  = (const float*)d_in[10];

    size_t smem = (size_t)SMEMF * sizeof(float);
    cudaFuncSetAttribute(lstm2_pipe, cudaFuncAttributeMaxDynamicSharedMemorySize, (int)smem);
    lstm2_pipe<<<CTAS, NTHR, smem>>>(x, w_ih0, w_hh0, b_ih0, b_hh0,
                                     w_ih1, w_hh1, b_ih1, b_hh1,
                                     fc_w, fc_b, (float*)d_out);
}

// round 13
// speedup vs baseline: 1.0110x; 1.0110x over previous
#include <cuda_runtime.h>
#include <cstdint>

#define SS   512
#define OUTN 12
#define CTAS 128
#define NTHR 256
#define XCH  64

typedef uint32_t u32;

__device__ __forceinline__ float tanhax(float x) {
    float r; asm("tanh.approx.f32 %0, %1;" : "=f"(r) : "f"(x)); return r;
}
__device__ __forceinline__ float sig_t(float x) { return fmaf(0.5f, tanhax(0.5f * x), 0.5f); }

__device__ __forceinline__ u32 bf16rn(float x) {      // f32 -> bf16 bits (RN)
    u32 u = __float_as_uint(x);
    u += 0x7fffu + ((u >> 16) & 1u);
    return u >> 16;
}
__device__ __forceinline__ u32 pkbf(float lo, float hi) {   // bf16x2, lo in low half
    return bf16rn(lo) | (bf16rn(hi) << 16);
}
__device__ __forceinline__ float bfres(float v) {     // residual after bf16 rounding
    return v - __uint_as_float(bf16rn(v) << 16);
}
// gate-interleaved column n = 4*u + g  ->  global weight row g*64 + u
__device__ __forceinline__ int grow(int n) { return (n & 3) * 64 + (n >> 2); }

__device__ __forceinline__ void mma16(float d[4], const u32 a[4], u32 b0, u32 b1) {
    asm volatile("mma.sync.aligned.m16n8k16.row.col.f32.bf16.bf16.f32 "
                 "{%0,%1,%2,%3}, {%4,%5,%6,%7}, {%8,%9}, {%0,%1,%2,%3};"
                 : "+f"(d[0]), "+f"(d[1]), "+f"(d[2]), "+f"(d[3])
                 : "r"(a[0]), "r"(a[1]), "r"(a[2]), "r"(a[3]), "r"(b0), "r"(b1));
}

// smem float offsets
#define OF_A0    0        // h0 frags: [2 slot][4 kt][32 lane][4 reg] u32
#define OF_A1    1024     // h1 frags, same shape
#define OF_XS    2048     // [XCH][16]
#define OF_HFIN  3072     // [16 b][64 u]
#define OF_SI0   4096     // [w][nt][lane][4]: bias0 n0, n1, wih0 n0, n1
#define OF_SI1   8192     // [w][nt][lane][2]: bias1 n0, n1
#define OF_W1H   10240    // Wih1 hi frag: [w][nt][kt][lane][2] u32
#define OF_L1F   18432    // Wih1 lo
#define OF_L0R   26624    // Whh0 lo
#define OF_L2R   34816    // Whh1 lo
#define SMEMF    43008    // 168 KB

__global__ void __launch_bounds__(NTHR, 1) lstm2_1bar(
    const float* __restrict__ x,
    const float* __restrict__ w_ih0, const float* __restrict__ w_hh0,
    const float* __restrict__ b_ih0, const float* __restrict__ b_hh0,
    const float* __restrict__ w_ih1, const float* __restrict__ w_hh1,
    const float* __restrict__ b_ih1, const float* __restrict__ b_hh1,
    const float* __restrict__ fc_w, const float* __restrict__ fc_b,
    float* __restrict__ out)
{
    extern __shared__ float sm[];
    u32*   A0   = (u32*)(sm + OF_A0);
    u32*   A1   = (u32*)(sm + OF_A1);
    float* xs   = sm + OF_XS;
    float* hfin = sm + OF_HFIN;
    float* si0  = sm + OF_SI0;
    float* si1  = sm + OF_SI1;
    u32*   w1h  = (u32*)(sm + OF_W1H);
    u32*   l1f  = (u32*)(sm + OF_L1F);
    u32*   l0r  = (u32*)(sm + OF_L0R);
    u32*   l2r  = (u32*)(sm + OF_L2R);

    const int tid  = threadIdx.x;
    const int lane = tid & 31;
    const int w    = tid >> 5;          // warp owns cols [32w, 32w+32)
    const int g    = lane >> 2;
    const int tg   = lane & 3;
    const int evn  = (tg & 1) == 0;
    const int rr   = g + 8 * (tg & 1);  // batch row this lane cells
    const int b0g  = blockIdx.x * 16;

    // ---------------- one-time staging ----------------
    for (int e = tid; e < 2048; e += NTHR) sm[e] = 0.f;   // zero A0+A1 (h(-1)=0)

    // hi frags for Whh0/Whh1 in regs; Wih1 hi + all lo residuals in smem.
    u32 rh0[4][4][2], rh2[4][4][2];
    const int fb = (w * 512 + lane) * 2;   // per-warp frag base (u32 idx)
#pragma unroll
    for (int nt = 0; nt < 4; nt++) {
        const int n  = w * 32 + nt * 8 + g;
        const int gr = grow(n);
#pragma unroll
        for (int kt = 0; kt < 4; kt++) {
            const int k0 = 16 * kt + 2 * tg;
            const int fo = fb + (nt * 4 + kt) * 64;
            // Whh0
            float v00 = w_hh0[gr * 64 + k0],     v01 = w_hh0[gr * 64 + k0 + 1];
            float v10 = w_hh0[gr * 64 + k0 + 8], v11 = w_hh0[gr * 64 + k0 + 9];
            rh0[nt][kt][0] = pkbf(v00, v01);
            rh0[nt][kt][1] = pkbf(v10, v11);
            l0r[fo + 0] = pkbf(bfres(v00), bfres(v01));
            l0r[fo + 1] = pkbf(bfres(v10), bfres(v11));
            // Whh1
            v00 = w_hh1[gr * 64 + k0];     v01 = w_hh1[gr * 64 + k0 + 1];
            v10 = w_hh1[gr * 64 + k0 + 8]; v11 = w_hh1[gr * 64 + k0 + 9];
            rh2[nt][kt][0] = pkbf(v00, v01);
            rh2[nt][kt][1] = pkbf(v10, v11);
            l2r[fo + 0] = pkbf(bfres(v00), bfres(v01));
            l2r[fo + 1] = pkbf(bfres(v10), bfres(v11));
            // Wih1 -> smem frags
            v00 = w_ih1[gr * 64 + k0];     v01 = w_ih1[gr * 64 + k0 + 1];
            v10 = w_ih1[gr * 64 + k0 + 8]; v11 = w_ih1[gr * 64 + k0 + 9];
            w1h[fo + 0] = pkbf(v00, v01);
            w1h[fo + 1] = pkbf(v10, v11);
            l1f[fo + 0] = pkbf(bfres(v00), bfres(v01));
            l1f[fo + 1] = pkbf(bfres(v10), bfres(v11));
        }
        // bias / input-weight tables for this warp's cols
        const int n0 = w * 32 + nt * 8 + 2 * tg, n1 = n0 + 1;
        const int g0 = grow(n0), g1 = grow(n1);
        float* p0 = si0 + (((w * 4 + nt) * 32) + lane) * 4;
        p0[0] = b_ih0[g0] + b_hh0[g0];
        p0[1] = b_ih0[g1] + b_hh0[g1];
        p0[2] = w_ih0[g0];                 // INPUT_SIZE == 1
        p0[3] = w_ih0[g1];
        float* p1 = si1 + (((w * 4 + nt) * 32) + lane) * 2;
        p1[0] = b_ih1[g0] + b_hh1[g0];
        p1[1] = b_ih1[g1] + b_hh1[g1];
    }

    // publish slots (same mapping as R10/R11)
    int pub_idx[4];
#pragma unroll
    for (int nt = 0; nt < 4; nt++) {
        const int kpn = 4 * w + nt;
        const int kt_ = kpn >> 3, kp8 = kpn & 7;
        const int lane_ = (rr & 7) * 4 + (kp8 & 3);
        const int reg = (kp8 >= 4 ? 2 : 0) + (rr >= 8 ? 1 : 0);
        pub_idx[nt] = (kt_ * 32 + lane_) * 4 + reg;
    }

    float c0[4] = {0.f, 0.f, 0.f, 0.f}, c1[4] = {0.f, 0.f, 0.f, 0.f};
    float hv1[4] = {0.f, 0.f, 0.f, 0.f};
    __syncthreads();

    // ---------- recurrence: iteration k computes h0[k] and h1[k-1] ----------
    // One __syncthreads per iteration. All inputs (h0[k-1], h1[k-2]) are
    // published before the iteration starts.
    for (int k = 0; k <= SS; k++) {
        if (k < SS && (k & (XCH - 1)) == 0) {   // refill x chunk [k, k+XCH)
            __syncthreads();
            for (int e = tid; e < 16 * XCH; e += NTHR) {
                int tc = e & (XCH - 1), b = e >> 6;
                xs[tc * 16 + b] = x[(size_t)(b0g + b) * SS + k + tc];
            }
            __syncthreads();
        }
        const u32* A0r = A0 + ((k + 1) & 1) * 512;   // h0[k-1]
        u32*       A0w = A0 + (k & 1) * 512;         // h0[k]
        const u32* A1r = A1 + (k & 1) * 512;         // h1[k-2]
        u32*       A1w = A1 + ((k + 1) & 1) * 512;   // h1[k-1]

        const int tloc = k & (XCH - 1);
        const float xg  = xs[tloc * 16 + g];         // stale at k==SS (unused)
        const float xg8 = xs[tloc * 16 + g + 8];

        // ---- D0 = b0 + wih0*x[k] ;  D1 = b1 ----
        float D0[4][4], D1[4][4];
#pragma unroll
        for (int nt = 0; nt < 4; nt++) {
            float4 ini = *(const float4*)(si0 + (((w * 4 + nt) * 32) + lane) * 4);
            D0[nt][0] = fmaf(ini.z, xg,  ini.x);
            D0[nt][1] = fmaf(ini.w, xg,  ini.y);
            D0[nt][2] = fmaf(ini.z, xg8, ini.x);
            D0[nt][3] = fmaf(ini.w, xg8, ini.y);
            float2 bi = *(const float2*)(si1 + (((w * 4 + nt) * 32) + lane) * 2);
            D1[nt][0] = bi.x; D1[nt][1] = bi.y;
            D1[nt][2] = bi.x; D1[nt][3] = bi.y;
        }

        // ---- all 96 mma: D0 += Whh0*h0[k-1]; D1 += Wih1*h0[k-1] + Whh1*h1[k-2]
        //      (a = h0[k-1] frag shared by Whh0 and Wih1; b = h1[k-2] frag)
#pragma unroll
        for (int kt = 0; kt < 4; kt++) {
            u32 a[4], b[4];
            *(uint4*)a = *(const uint4*)(A0r + (kt * 32 + lane) * 4);
            *(uint4*)b = *(const uint4*)(A1r + (kt * 32 + lane) * 4);
#pragma unroll
            for (int nt = 0; nt < 4; nt++) {
                mma16(D0[nt], a, rh0[nt][kt][0], rh0[nt][kt][1]);
                mma16(D1[nt], b, rh2[nt][kt][0], rh2[nt][kt][1]);
            }
#pragma unroll
            for (int nt = 0; nt < 4; nt++) {
                uint2 lp0 = *(const uint2*)(l0r + fb + (nt * 4 + kt) * 64);
                mma16(D0[nt], a, lp0.x, lp0.y);
                uint2 hp1 = *(const uint2*)(w1h + fb + (nt * 4 + kt) * 64);
                mma16(D1[nt], a, hp1.x, hp1.y);
            }
#pragma unroll
            for (int nt = 0; nt < 4; nt++) {
                uint2 lp2 = *(const uint2*)(l2r + fb + (nt * 4 + kt) * 64);
                mma16(D1[nt], b, lp2.x, lp2.y);
                uint2 lp1 = *(const uint2*)(l1f + fb + (nt * 4 + kt) * 64);
                mma16(D1[nt], a, lp1.x, lp1.y);
            }
        }

        // ---- cell 0 -> h0[k]  (D0 drained while D1 mma still in the pipe) ----
        if (k < SS) {
            float hv0[4];
#pragma unroll
            for (int nt = 0; nt < 4; nt++) {
                float s0 = evn ? D0[nt][2] : D0[nt][0];
                float s1 = evn ? D0[nt][3] : D0[nt][1];
                float r0 = __shfl_xor_sync(0xffffffffu, s0, 1);
                float r1 = __shfl_xor_sync(0xffffffffu, s1, 1);
                float iv = evn ? D0[nt][0] : r0;
                float fv = evn ? D0[nt][1] : r1;
                float gv = evn ? r0        : D0[nt][2];
                float ov = evn ? r1        : D0[nt][3];
                float cc = fmaf(sig_t(fv), c0[nt], sig_t(iv) * tanhax(gv));
                c0[nt] = cc;
                hv0[nt] = sig_t(ov) * tanhax(cc);
            }
#pragma unroll
            for (int nt = 0; nt < 4; nt++) {
                float oth = __shfl_xor_sync(0xffffffffu, hv0[nt], 2);
                if (tg < 2) A0w[pub_idx[nt]] = pkbf(hv0[nt], oth);
            }
        }

        // ---- cell 1 -> h1[k-1] ----
        if (k >= 1) {
#pragma unroll
            for (int nt = 0; nt < 4; nt++) {
                float s0 = evn ? D1[nt][2] : D1[nt][0];
                float s1 = evn ? D1[nt][3] : D1[nt][1];
                float r0 = __shfl_xor_sync(0xffffffffu, s0, 1);
                float r1 = __shfl_xor_sync(0xffffffffu, s1, 1);
                float iv = evn ? D1[nt][0] : r0;
                float fv = evn ? D1[nt][1] : r1;
                float gv = evn ? r0        : D1[nt][2];
                float ov = evn ? r1        : D1[nt][3];
                float cc = fmaf(sig_t(fv), c1[nt], sig_t(iv) * tanhax(gv));
                c1[nt] = cc;
                hv1[nt] = sig_t(ov) * tanhax(cc);
            }
#pragma unroll
            for (int nt = 0; nt < 4; nt++) {
                float oth = __shfl_xor_sync(0xffffffffu, hv1[nt], 2);
                if (tg < 2) A1w[pub_idx[nt]] = pkbf(hv1[nt], oth);
            }
        }
        __syncthreads();     // single barrier: all slot hazards separated here
    }

    // ---------------- epilogue (hv1 = h1[SS-1], full fp32) ----------------
#pragma unroll
    for (int nt = 0; nt < 4; nt++)
        hfin[rr * 64 + (w * 8 + 2 * nt + (tg >> 1))] = hv1[nt];
    __syncthreads();

    for (int idx = tid; idx < 16 * OUTN; idx += NTHR) {
        int b = idx / OUTN, o = idx - b * OUTN;
        float s = fc_b[o];
#pragma unroll 16
        for (int uu = 0; uu < 64; uu++)
            s += hfin[b * 64 + uu] * fc_w[o * 64 + uu];
        out[(size_t)(b0g + b) * OUTN + o] = s;
    }
}

extern "C" void kernel_launch(void* const* d_in, const int* in_sizes, int n_in,
                              void* d_out, int out_size) {
    (void)in_sizes; (void)n_in; (void)out_size;
    const float* x     = (const float*)d_in[0];
    const float* w_ih0 = (const float*)d_in[1];
    const float* w_hh0 = (const float*)d_in[2];
    const float* b_ih0 = (const float*)d_in[3];
    const float* b_hh0 = (const float*)d_in[4];
    const float* w_ih1 = (const float*)d_in[5];
    const float* w_hh1 = (const float*)d_in[6];
    const float* b_ih1 = (const float*)d_in[7];
    const float* b_hh1 = (const float*)d_in[8];
    const float* fc_w  = (const float*)d_in[9];
    const float* fc_b  = (const float*)d_in[10];

    size_t smem = (size_t)SMEMF * sizeof(float);
    cudaFuncSetAttribute(lstm2_1bar, cudaFuncAttributeMaxDynamicSharedMemorySize, (int)smem);
    lstm2_1bar<<<CTAS, NTHR, smem>>>(x, w_ih0, w_hh0, b_ih0, b_hh0,
                                     w_ih1, w_hh1, b_ih1, b_hh1,
                                     fc_w, fc_b, (float*)d_out);
}

// round 15
// speedup vs baseline: 1.0811x; 1.0693x over previous
#include <cuda_runtime.h>
#include <cstdint>

#define SS   512
#define OUTN 12
#define CTAS 128
#define NTHR 512
#define XCH  64

typedef uint32_t u32;

__device__ __forceinline__ float tanhax(float x) {
    float r; asm("tanh.approx.f32 %0, %1;" : "=f"(r) : "f"(x)); return r;
}
__device__ __forceinline__ float sig_t(float x) { return fmaf(0.5f, tanhax(0.5f * x), 0.5f); }

__device__ __forceinline__ u32 bf16rn(float x) {      // f32 -> bf16 bits (RN)
    u32 u = __float_as_uint(x);
    u += 0x7fffu + ((u >> 16) & 1u);
    return u >> 16;
}
__device__ __forceinline__ u32 pkbf(float lo, float hi) {   // bf16x2, lo in low half
    return bf16rn(lo) | (bf16rn(hi) << 16);
}
__device__ __forceinline__ float bfres(float v) {     // residual after bf16 rounding
    return v - __uint_as_float(bf16rn(v) << 16);
}
// gate-interleaved column n = 4*u + g  ->  global weight row g*64 + u
__device__ __forceinline__ int grow(int n) { return (n & 3) * 64 + (n >> 2); }

__device__ __forceinline__ void mma16(float d[4], const u32 a[4], u32 b0, u32 b1) {
    asm volatile("mma.sync.aligned.m16n8k16.row.col.f32.bf16.bf16.f32 "
                 "{%0,%1,%2,%3}, {%4,%5,%6,%7}, {%8,%9}, {%0,%1,%2,%3};"
                 : "+f"(d[0]), "+f"(d[1]), "+f"(d[2]), "+f"(d[3])
                 : "r"(a[0]), "r"(a[1]), "r"(a[2]), "r"(a[3]), "r"(b0), "r"(b1));
}

// smem float offsets
#define OF_A0    0        // h0 frags: [2 slot][4 kt][32 lane][4 reg] u32
#define OF_A1    1024     // h1 frags, same shape
#define OF_XS    2048     // [XCH][16]
#define OF_HFIN  3072     // [16 b][64 u]
#define OF_SI0   4096     // [w16][nt2][lane][4]: bias0 n0, n1, wih0 n0, n1
#define OF_SI1   8192     // [w16][nt2][lane][2]: bias1 n0, n1
#define OF_W1H   10240    // Wih1 hi frag: [w16][nt2][kt4][lane][2] u32
#define OF_L1F   18432    // Wih1 lo
#define OF_L0R   26624    // Whh0 lo
#define OF_L2R   34816    // Whh1 lo
#define SMEMF    43008    // 168 KB

__global__ void __launch_bounds__(NTHR, 1) lstm2_16w(
    const float* __restrict__ x,
    const float* __restrict__ w_ih0, const float* __restrict__ w_hh0,
    const float* __restrict__ b_ih0, const float* __restrict__ b_hh0,
    const float* __restrict__ w_ih1, const float* __restrict__ w_hh1,
    const float* __restrict__ b_ih1, const float* __restrict__ b_hh1,
    const float* __restrict__ fc_w, const float* __restrict__ fc_b,
    float* __restrict__ out)
{
    extern __shared__ float sm[];
    u32*   A0   = (u32*)(sm + OF_A0);
    u32*   A1   = (u32*)(sm + OF_A1);
    float* xs   = sm + OF_XS;
    float* hfin = sm + OF_HFIN;
    float* si0  = sm + OF_SI0;
    float* si1  = sm + OF_SI1;
    u32*   w1h  = (u32*)(sm + OF_W1H);
    u32*   l1f  = (u32*)(sm + OF_L1F);
    u32*   l0r  = (u32*)(sm + OF_L0R);
    u32*   l2r  = (u32*)(sm + OF_L2R);

    const int tid  = threadIdx.x;
    const int lane = tid & 31;
    const int w    = tid >> 5;          // 16 warps; warp owns cols [16w, 16w+16)
    const int g    = lane >> 2;
    const int tg   = lane & 3;
    const int evn  = (tg & 1) == 0;
    const int rr   = g + 8 * (tg & 1);  // batch row this lane cells
    const int b0g  = blockIdx.x * 16;

    // ---------------- one-time staging ----------------
    for (int e = tid; e < 2048; e += NTHR) sm[e] = 0.f;   // zero A0+A1 (h(-1)=0)

    // hi frags for Whh0/Whh1 in regs; Wih1 hi + all lo residuals in smem.
    u32 rh0[2][4][2], rh2[2][4][2];
    const int fb = (w * 256 + lane) * 2;   // per-warp frag base (u32 idx)
#pragma unroll
    for (int nt = 0; nt < 2; nt++) {
        const int n  = w * 16 + nt * 8 + g;
        const int gr = grow(n);
#pragma unroll
        for (int kt = 0; kt < 4; kt++) {
            const int k0 = 16 * kt + 2 * tg;
            const int fo = fb + (nt * 4 + kt) * 64;
            // Whh0
            float v00 = w_hh0[gr * 64 + k0],     v01 = w_hh0[gr * 64 + k0 + 1];
            float v10 = w_hh0[gr * 64 + k0 + 8], v11 = w_hh0[gr * 64 + k0 + 9];
            rh0[nt][kt][0] = pkbf(v00, v01);
            rh0[nt][kt][1] = pkbf(v10, v11);
            l0r[fo + 0] = pkbf(bfres(v00), bfres(v01));
            l0r[fo + 1] = pkbf(bfres(v10), bfres(v11));
            // Whh1
            v00 = w_hh1[gr * 64 + k0];     v01 = w_hh1[gr * 64 + k0 + 1];
            v10 = w_hh1[gr * 64 + k0 + 8]; v11 = w_hh1[gr * 64 + k0 + 9];
            rh2[nt][kt][0] = pkbf(v00, v01);
            rh2[nt][kt][1] = pkbf(v10, v11);
            l2r[fo + 0] = pkbf(bfres(v00), bfres(v01));
            l2r[fo + 1] = pkbf(bfres(v10), bfres(v11));
            // Wih1 -> smem frags
            v00 = w_ih1[gr * 64 + k0];     v01 = w_ih1[gr * 64 + k0 + 1];
            v10 = w_ih1[gr * 64 + k0 + 8]; v11 = w_ih1[gr * 64 + k0 + 9];
            w1h[fo + 0] = pkbf(v00, v01);
            w1h[fo + 1] = pkbf(v10, v11);
            l1f[fo + 0] = pkbf(bfres(v00), bfres(v01));
            l1f[fo + 1] = pkbf(bfres(v10), bfres(v11));
        }
        // bias / input-weight tables for this warp's cols
        const int n0 = w * 16 + nt * 8 + 2 * tg, n1 = n0 + 1;
        const int g0 = grow(n0), g1 = grow(n1);
        float* p0 = si0 + (((w * 2 + nt) * 32) + lane) * 4;
        p0[0] = b_ih0[g0] + b_hh0[g0];
        p0[1] = b_ih0[g1] + b_hh0[g1];
        p0[2] = w_ih0[g0];                 // INPUT_SIZE == 1
        p0[3] = w_ih0[g1];
        float* p1 = si1 + (((w * 2 + nt) * 32) + lane) * 2;
        p1[0] = b_ih1[g0] + b_hh1[g0];
        p1[1] = b_ih1[g1] + b_hh1[g1];
    }

    // publish slots: unit-pair kpn = 2w + nt
    int pub_idx[2];
#pragma unroll
    for (int nt = 0; nt < 2; nt++) {
        const int kpn = 2 * w + nt;
        const int kt_ = kpn >> 3, kp8 = kpn & 7;
        const int lane_ = (rr & 7) * 4 + (kp8 & 3);
        const int reg = (kp8 >= 4 ? 2 : 0) + (rr >= 8 ? 1 : 0);
        pub_idx[nt] = (kt_ * 32 + lane_) * 4 + reg;
    }

    float c0[2] = {0.f, 0.f}, c1[2] = {0.f, 0.f};
    float hv1[2] = {0.f, 0.f};
    __syncthreads();

    // ---------- recurrence: iteration k computes h0[k] and h1[k-1] ----------
    for (int k = 0; k <= SS; k++) {
        if (k < SS && (k & (XCH - 1)) == 0) {   // refill x chunk [k, k+XCH)
            __syncthreads();
            for (int e = tid; e < 16 * XCH; e += NTHR) {
                int tc = e & (XCH - 1), b = e >> 6;
                xs[tc * 16 + b] = x[(size_t)(b0g + b) * SS + k + tc];
            }
            __syncthreads();
        }
        const u32* A0r = A0 + ((k + 1) & 1) * 512;   // h0[k-1]
        u32*       A0w = A0 + (k & 1) * 512;         // h0[k]
        const u32* A1r = A1 + (k & 1) * 512;         // h1[k-2]
        u32*       A1w = A1 + ((k + 1) & 1) * 512;   // h1[k-1]

        const int tloc = k & (XCH - 1);
        const float xg  = xs[tloc * 16 + g];
        const float xg8 = xs[tloc * 16 + g + 8];

        // ---- D0 = b0 + wih0*x[k] ;  D1 = b1 ----
        float D0[2][4], D1[2][4];
#pragma unroll
        for (int nt = 0; nt < 2; nt++) {
            float4 ini = *(const float4*)(si0 + (((w * 2 + nt) * 32) + lane) * 4);
            D0[nt][0] = fmaf(ini.z, xg,  ini.x);
            D0[nt][1] = fmaf(ini.w, xg,  ini.y);
            D0[nt][2] = fmaf(ini.z, xg8, ini.x);
            D0[nt][3] = fmaf(ini.w, xg8, ini.y);
            float2 bi = *(const float2*)(si1 + (((w * 2 + nt) * 32) + lane) * 2);
            D1[nt][0] = bi.x; D1[nt][1] = bi.y;
            D1[nt][2] = bi.x; D1[nt][3] = bi.y;
        }

        // ---- 48 mma: D0 += Whh0*h0[k-1]; D1 += Wih1*h0[k-1] + Whh1*h1[k-2] ----
#pragma unroll
        for (int kt = 0; kt < 4; kt++) {
            u32 a[4], b[4];
            *(uint4*)a = *(const uint4*)(A0r + (kt * 32 + lane) * 4);
            *(uint4*)b = *(const uint4*)(A1r + (kt * 32 + lane) * 4);
#pragma unroll
            for (int nt = 0; nt < 2; nt++) {
                mma16(D0[nt], a, rh0[nt][kt][0], rh0[nt][kt][1]);
                mma16(D1[nt], b, rh2[nt][kt][0], rh2[nt][kt][1]);
            }
#pragma unroll
            for (int nt = 0; nt < 2; nt++) {
                uint2 lp0 = *(const uint2*)(l0r + fb + (nt * 4 + kt) * 64);
                mma16(D0[nt], a, lp0.x, lp0.y);
                uint2 hp1 = *(const uint2*)(w1h + fb + (nt * 4 + kt) * 64);
                mma16(D1[nt], a, hp1.x, hp1.y);
            }
#pragma unroll
            for (int nt = 0; nt < 2; nt++) {
                uint2 lp2 = *(const uint2*)(l2r + fb + (nt * 4 + kt) * 64);
                mma16(D1[nt], b, lp2.x, lp2.y);
                uint2 lp1 = *(const uint2*)(l1f + fb + (nt * 4 + kt) * 64);
                mma16(D1[nt], a, lp1.x, lp1.y);
            }
        }

        // ---- cell 0 -> h0[k] ----
        if (k < SS) {
            float hv0[2];
#pragma unroll
            for (int nt = 0; nt < 2; nt++) {
                float s0 = evn ? D0[nt][2] : D0[nt][0];
                float s1 = evn ? D0[nt][3] : D0[nt][1];
                float r0 = __shfl_xor_sync(0xffffffffu, s0, 1);
                float r1 = __shfl_xor_sync(0xffffffffu, s1, 1);
                float iv = evn ? D0[nt][0] : r0;
                float fv = evn ? D0[nt][1] : r1;
                float gv = evn ? r0        : D0[nt][2];
                float ov = evn ? r1        : D0[nt][3];
                float cc = fmaf(sig_t(fv), c0[nt], sig_t(iv) * tanhax(gv));
                c0[nt] = cc;
                hv0[nt] = sig_t(ov) * tanhax(cc);
            }
#pragma unroll
            for (int nt = 0; nt < 2; nt++) {
                float oth = __shfl_xor_sync(0xffffffffu, hv0[nt], 2);
                if (tg < 2) A0w[pub_idx[nt]] = pkbf(hv0[nt], oth);
            }
        }

        // ---- cell 1 -> h1[k-1] ----
        if (k >= 1) {
#pragma unroll
            for (int nt = 0; nt < 2; nt++) {
                float s0 = evn ? D1[nt][2] : D1[nt][0];
                float s1 = evn ? D1[nt][3] : D1[nt][1];
                float r0 = __shfl_xor_sync(0xffffffffu, s0, 1);
                float r1 = __shfl_xor_sync(0xffffffffu, s1, 1);
                float iv = evn ? D1[nt][0] : r0;
                float fv = evn ? D1[nt][1] : r1;
                float gv = evn ? r0        : D1[nt][2];
                float ov = evn ? r1        : D1[nt][3];
                float cc = fmaf(sig_t(fv), c1[nt], sig_t(iv) * tanhax(gv));
                c1[nt] = cc;
                hv1[nt] = sig_t(ov) * tanhax(cc);
            }
#pragma unroll
            for (int nt = 0; nt < 2; nt++) {
                float oth = __shfl_xor_sync(0xffffffffu, hv1[nt], 2);
                if (tg < 2) A1w[pub_idx[nt]] = pkbf(hv1[nt], oth);
            }
        }
        __syncthreads();     // single barrier: all slot hazards separated here
    }

    // ---------------- epilogue (hv1 = h1[SS-1], full fp32) ----------------
#pragma unroll
    for (int nt = 0; nt < 2; nt++)
        hfin[rr * 64 + (w * 4 + 2 * nt + (tg >> 1))] = hv1[nt];
    __syncthreads();

    for (int idx = tid; idx < 16 * OUTN; idx += NTHR) {
        int b = idx / OUTN, o = idx - b * OUTN;
        float s = fc_b[o];
#pragma unroll 16
        for (int uu = 0; uu < 64; uu++)
            s += hfin[b * 64 + uu] * fc_w[o * 64 + uu];
        out[(size_t)(b0g + b) * OUTN + o] = s;
    }
}

extern "C" void kernel_launch(void* const* d_in, const int* in_sizes, int n_in,
                              void* d_out, int out_size) {
    (void)in_sizes; (void)n_in; (void)out_size;
    const float* x     = (const float*)d_in[0];
    const float* w_ih0 = (const float*)d_in[1];
    const float* w_hh0 = (const float*)d_in[2];
    const float* b_ih0 = (const float*)d_in[3];
    const float* b_hh0 = (const float*)d_in[4];
    const float* w_ih1 = (const float*)d_in[5];
    const float* w_hh1 = (const float*)d_in[6];
    const float* b_ih1 = (const float*)d_in[7];
    const float* b_hh1 = (const float*)d_in[8];
    const float* fc_w  = (const float*)d_in[9];
    const float* fc_b  = (const float*)d_in[10];

    size_t smem = (size_t)SMEMF * sizeof(float);
    cudaFuncSetAttribute(lstm2_16w, cudaFuncAttributeMaxDynamicSharedMemorySize, (int)smem);
    lstm2_16w<<<CTAS, NTHR, smem>>>(x, w_ih0, w_hh0, b_ih0, b_hh0,
                                    w_ih1, w_hh1, b_ih1, b_hh1,
                                    fc_w, fc_b, (float*)d_out);
}

// round 16
// speedup vs baseline: 1.8459x; 1.7074x over previous
#include <cuda_runtime.h>
#include <cuda_fp16.h>
#include <cstdint>

#define SS   512
#define OUTN 12
#define CTAS 128
#define NTHR 512
#define XCH  64

typedef uint32_t u32;

__device__ __forceinline__ float tanhax(float x) {
    float r; asm("tanh.approx.f32 %0, %1;" : "=f"(r) : "f"(x)); return r;
}
__device__ __forceinline__ float sig_t(float x) { return fmaf(0.5f, tanhax(0.5f * x), 0.5f); }

__device__ __forceinline__ u32 pkh(float lo, float hi) {   // fp16x2, lo in low half
    __half2 h = __floats2half2_rn(lo, hi);
    return *(u32*)&h;
}
__device__ __forceinline__ unsigned short h16(float v) {
    __half h = __float2half_rn(v);
    return *(unsigned short*)&h;
}
// gate-interleaved column n = 4*u + g  ->  global weight row g*64 + u
__device__ __forceinline__ int grow(int n) { return (n & 3) * 64 + (n >> 2); }

__device__ __forceinline__ void mma16(float d[4], const u32 a[4], u32 b0, u32 b1) {
    asm volatile("mma.sync.aligned.m16n8k16.row.col.f32.f16.f16.f32 "
                 "{%0,%1,%2,%3}, {%4,%5,%6,%7}, {%8,%9}, {%0,%1,%2,%3};"
                 : "+f"(d[0]), "+f"(d[1]), "+f"(d[2]), "+f"(d[3])
                 : "r"(a[0]), "r"(a[1]), "r"(a[2]), "r"(a[3]), "r"(b0), "r"(b1));
}

// smem float offsets
#define OF_A0    0        // h0 frags: [2 slot][4 kt][32 lane][4 reg] u32 (fp16x2)
#define OF_A1    1024     // h1 frags, same shape
#define OF_XS    2048     // [XCH][16]
#define OF_HFIN  3072     // [16 b][64 u]
#define OF_SI0   4096     // [w16][nt2][lane][4]: bias0 n0, n1, wih0 n0, n1
#define OF_SI1   8192     // [w16][nt2][lane][2]: bias1 n0, n1
#define SMEMF    10240    // 40 KB

__global__ void __launch_bounds__(NTHR, 1) lstm2_fp16(
    const float* __restrict__ x,
    const float* __restrict__ w_ih0, const float* __restrict__ w_hh0,
    const float* __restrict__ b_ih0, const float* __restrict__ b_hh0,
    const float* __restrict__ w_ih1, const float* __restrict__ w_hh1,
    const float* __restrict__ b_ih1, const float* __restrict__ b_hh1,
    const float* __restrict__ fc_w, const float* __restrict__ fc_b,
    float* __restrict__ out)
{
    extern __shared__ float sm[];
    u32*   A0   = (u32*)(sm + OF_A0);
    u32*   A1   = (u32*)(sm + OF_A1);
    float* xs   = sm + OF_XS;
    float* hfin = sm + OF_HFIN;
    float* si0  = sm + OF_SI0;
    float* si1  = sm + OF_SI1;

    const int tid  = threadIdx.x;
    const int lane = tid & 31;
    const int w    = tid >> 5;          // 16 warps; warp owns cols [16w, 16w+16)
    const int g    = lane >> 2;
    const int tg   = lane & 3;
    const int evn  = (tg & 1) == 0;
    const int rr   = g + 8 * (tg & 1);  // batch row this lane cells
    const int uoff = tg >> 1;           // unit-within-pair
    const int b0g  = blockIdx.x * 16;

    // ---------------- one-time staging ----------------
    for (int e = tid; e < 2048; e += NTHR) sm[e] = 0.f;   // zero A0+A1 (h(-1)=0)

    // All three weight matrices as fp16 register fragments.
    u32 rh0[2][4][2], rh2[2][4][2], rh1[2][4][2];
#pragma unroll
    for (int nt = 0; nt < 2; nt++) {
        const int n  = w * 16 + nt * 8 + g;
        const int gr = grow(n);
#pragma unroll
        for (int kt = 0; kt < 4; kt++) {
            const int k0 = 16 * kt + 2 * tg;
            rh0[nt][kt][0] = pkh(w_hh0[gr * 64 + k0],     w_hh0[gr * 64 + k0 + 1]);
            rh0[nt][kt][1] = pkh(w_hh0[gr * 64 + k0 + 8], w_hh0[gr * 64 + k0 + 9]);
            rh2[nt][kt][0] = pkh(w_hh1[gr * 64 + k0],     w_hh1[gr * 64 + k0 + 1]);
            rh2[nt][kt][1] = pkh(w_hh1[gr * 64 + k0 + 8], w_hh1[gr * 64 + k0 + 9]);
            rh1[nt][kt][0] = pkh(w_ih1[gr * 64 + k0],     w_ih1[gr * 64 + k0 + 1]);
            rh1[nt][kt][1] = pkh(w_ih1[gr * 64 + k0 + 8], w_ih1[gr * 64 + k0 + 9]);
        }
        // bias / input-weight tables for this warp's cols
        const int n0 = w * 16 + nt * 8 + 2 * tg, n1 = n0 + 1;
        const int g0 = grow(n0), g1 = grow(n1);
        float* p0 = si0 + (((w * 2 + nt) * 32) + lane) * 4;
        p0[0] = b_ih0[g0] + b_hh0[g0];
        p0[1] = b_ih0[g1] + b_hh0[g1];
        p0[2] = w_ih0[g0];                 // INPUT_SIZE == 1
        p0[3] = w_ih0[g1];
        float* p1 = si1 + (((w * 2 + nt) * 32) + lane) * 2;
        p1[0] = b_ih1[g0] + b_hh1[g0];
        p1[1] = b_ih1[g1] + b_hh1[g1];
    }

    // publish word slots: unit-pair kpn = 2w + nt
    int pub_idx[2];
#pragma unroll
    for (int nt = 0; nt < 2; nt++) {
        const int kpn = 2 * w + nt;
        const int kt_ = kpn >> 3, kp8 = kpn & 7;
        const int lane_ = (rr & 7) * 4 + (kp8 & 3);
        const int reg = (kp8 >= 4 ? 2 : 0) + (rr >= 8 ? 1 : 0);
        pub_idx[nt] = (kt_ * 32 + lane_) * 4 + reg;
    }

    float c0[2] = {0.f, 0.f}, c1[2] = {0.f, 0.f};
    float hv1[2] = {0.f, 0.f};
    __syncthreads();

    // ---------- recurrence: iteration k computes h0[k] and h1[k-1] ----------
    for (int k = 0; k <= SS; k++) {
        if (k < SS && (k & (XCH - 1)) == 0) {   // refill x chunk [k, k+XCH)
            __syncthreads();
            for (int e = tid; e < 16 * XCH; e += NTHR) {
                int tc = e & (XCH - 1), b = e >> 6;
                xs[tc * 16 + b] = x[(size_t)(b0g + b) * SS + k + tc];
            }
            __syncthreads();
        }
        const u32* A0r = A0 + ((k + 1) & 1) * 512;   // h0[k-1]
        u32*       A0w = A0 + (k & 1) * 512;         // h0[k]
        const u32* A1r = A1 + (k & 1) * 512;         // h1[k-2]
        u32*       A1w = A1 + ((k + 1) & 1) * 512;   // h1[k-1]

        const int tloc = k & (XCH - 1);
        const float xg  = xs[tloc * 16 + g];
        const float xg8 = xs[tloc * 16 + g + 8];

        // ---- D0 = b0 + wih0*x[k] ;  D1a = b1 ;  D1b = 0 ----
        float D0[2][4], D1a[2][4], D1b[2][4];
#pragma unroll
        for (int nt = 0; nt < 2; nt++) {
            float4 ini = *(const float4*)(si0 + (((w * 2 + nt) * 32) + lane) * 4);
            D0[nt][0] = fmaf(ini.z, xg,  ini.x);
            D0[nt][1] = fmaf(ini.w, xg,  ini.y);
            D0[nt][2] = fmaf(ini.z, xg8, ini.x);
            D0[nt][3] = fmaf(ini.w, xg8, ini.y);
            float2 bi = *(const float2*)(si1 + (((w * 2 + nt) * 32) + lane) * 2);
            D1a[nt][0] = bi.x; D1a[nt][1] = bi.y;
            D1a[nt][2] = bi.x; D1a[nt][3] = bi.y;
            D1b[nt][0] = 0.f; D1b[nt][1] = 0.f;
            D1b[nt][2] = 0.f; D1b[nt][3] = 0.f;
        }

        // ---- 24 mma: D0 += Whh0*h0[k-1]; D1a += Whh1*h1[k-2]; D1b += Wih1*h0[k-1]
        //      three independent accumulator chains, one hit per kt each ----
#pragma unroll
        for (int kt = 0; kt < 4; kt++) {
            u32 a[4], b[4];
            *(uint4*)a = *(const uint4*)(A0r + (kt * 32 + lane) * 4);
            *(uint4*)b = *(const uint4*)(A1r + (kt * 32 + lane) * 4);
#pragma unroll
            for (int nt = 0; nt < 2; nt++) {
                mma16(D0[nt],  a, rh0[nt][kt][0], rh0[nt][kt][1]);
                mma16(D1a[nt], b, rh2[nt][kt][0], rh2[nt][kt][1]);
                mma16(D1b[nt], a, rh1[nt][kt][0], rh1[nt][kt][1]);
            }
        }

        // ---- cell 0 -> h0[k]  (direct fp16 publish, no shfl) ----
        if (k < SS) {
#pragma unroll
            for (int nt = 0; nt < 2; nt++) {
                float s0 = evn ? D0[nt][2] : D0[nt][0];
                float s1 = evn ? D0[nt][3] : D0[nt][1];
                float r0 = __shfl_xor_sync(0xffffffffu, s0, 1);
                float r1 = __shfl_xor_sync(0xffffffffu, s1, 1);
                float iv = evn ? D0[nt][0] : r0;
                float fv = evn ? D0[nt][1] : r1;
                float gv = evn ? r0        : D0[nt][2];
                float ov = evn ? r1        : D0[nt][3];
                float cc = fmaf(sig_t(fv), c0[nt], sig_t(iv) * tanhax(gv));
                c0[nt] = cc;
                float hv0 = sig_t(ov) * tanhax(cc);
                *(volatile unsigned short*)((char*)A0w + pub_idx[nt] * 4 + uoff * 2) = h16(hv0);
            }
        }

        // ---- cell 1 -> h1[k-1] ----
        if (k >= 1) {
#pragma unroll
            for (int nt = 0; nt < 2; nt++) {
                float m0 = D1a[nt][0] + D1b[nt][0];
                float m1 = D1a[nt][1] + D1b[nt][1];
                float m2 = D1a[nt][2] + D1b[nt][2];
                float m3 = D1a[nt][3] + D1b[nt][3];
                float s0 = evn ? m2 : m0;
                float s1 = evn ? m3 : m1;
                float r0 = __shfl_xor_sync(0xffffffffu, s0, 1);
                float r1 = __shfl_xor_sync(0xffffffffu, s1, 1);
                float iv = evn ? m0 : r0;
                float fv = evn ? m1 : r1;
                float gv = evn ? r0 : m2;
                float ov = evn ? r1 : m3;
                float cc = fmaf(sig_t(fv), c1[nt], sig_t(iv) * tanhax(gv));
                c1[nt] = cc;
                hv1[nt] = sig_t(ov) * tanhax(cc);
                *(volatile unsigned short*)((char*)A1w + pub_idx[nt] * 4 + uoff * 2) = h16(hv1[nt]);
            }
        }
        __syncthreads();     // single barrier: all slot hazards separated here
    }

    // ---------------- epilogue (hv1 = h1[SS-1], full fp32) ----------------
#pragma unroll
    for (int nt = 0; nt < 2; nt++)
        hfin[rr * 64 + (w * 4 + 2 * nt + uoff)] = hv1[nt];
    __syncthreads();

    for (int idx = tid; idx < 16 * OUTN; idx += NTHR) {
        int b = idx / OUTN, o = idx - b * OUTN;
        float s = fc_b[o];
#pragma unroll 16
        for (int uu = 0; uu < 64; uu++)
            s += hfin[b * 64 + uu] * fc_w[o * 64 + uu];
        out[(size_t)(b0g + b) * OUTN + o] = s;
    }
}

extern "C" void kernel_launch(void* const* d_in, const int* in_sizes, int n_in,
                              void* d_out, int out_size) {
    (void)in_sizes; (void)n_in; (void)out_size;
    const float* x     = (const float*)d_in[0];
    const float* w_ih0 = (const float*)d_in[1];
    const float* w_hh0 = (const float*)d_in[2];
    const float* b_ih0 = (const float*)d_in[3];
    const float* b_hh0 = (const float*)d_in[4];
    const float* w_ih1 = (const float*)d_in[5];
    const float* w_hh1 = (const float*)d_in[6];
    const float* b_ih1 = (const float*)d_in[7];
    const float* b_hh1 = (const float*)d_in[8];
    const float* fc_w  = (const float*)d_in[9];
    const float* fc_b  = (const float*)d_in[10];

    size_t smem = (size_t)SMEMF * sizeof(float);
    cudaFuncSetAttribute(lstm2_fp16, cudaFuncAttributeMaxDynamicSharedMemorySize, (int)smem);
    lstm2_fp16<<<CTAS, NTHR, smem>>>(x, w_ih0, w_hh0, b_ih0, b_hh0,
                                     w_ih1, w_hh1, b_ih1, b_hh1,
                                     fc_w, fc_b, (float*)d_out);
}

// round 17
// speedup vs baseline: 2.1892x; 1.1860x over previous
#include <cuda_runtime.h>
#include <cuda_fp16.h>
#include <cstdint>

#define SS   512
#define OUTN 12
#define CTAS 128
#define NTHR 512

typedef uint32_t u32;

__device__ __forceinline__ float tanhax(float x) {
    float r; asm("tanh.approx.f32 %0, %1;" : "=f"(r) : "f"(x)); return r;
}
__device__ __forceinline__ float sig_t(float x) { return fmaf(0.5f, tanhax(0.5f * x), 0.5f); }

__device__ __forceinline__ u32 pkh(float lo, float hi) {   // fp16x2, lo in low half
    __half2 h = __floats2half2_rn(lo, hi);
    return *(u32*)&h;
}
__device__ __forceinline__ unsigned short h16(float v) {
    __half h = __float2half_rn(v);
    return *(unsigned short*)&h;
}

__device__ __forceinline__ void mma16(float d[4], const u32 a[4], u32 b0, u32 b1) {
    asm volatile("mma.sync.aligned.m16n8k16.row.col.f32.f16.f16.f32 "
                 "{%0,%1,%2,%3}, {%4,%5,%6,%7}, {%8,%9}, {%0,%1,%2,%3};"
                 : "+f"(d[0]), "+f"(d[1]), "+f"(d[2]), "+f"(d[3])
                 : "r"(a[0]), "r"(a[1]), "r"(a[2]), "r"(a[3]), "r"(b0), "r"(b1));
}

// smem float offsets
#define OF_A0    0        // h0 frags: [2 slot][4 kt][32 lane][4 reg] u32 (fp16x2)
#define OF_A1    1024     // h1 frags, same shape
#define OF_XS    2048     // [512 t][16 b]  -- entire x staged once
#define OF_HFIN  10240    // [16 b][64 u]
#define SMEMF    11264    // 44 KB

__global__ void __launch_bounds__(NTHR, 1) lstm2_ga(
    const float* __restrict__ x,
    const float* __restrict__ w_ih0, const float* __restrict__ w_hh0,
    const float* __restrict__ b_ih0, const float* __restrict__ b_hh0,
    const float* __restrict__ w_ih1, const float* __restrict__ w_hh1,
    const float* __restrict__ b_ih1, const float* __restrict__ b_hh1,
    const float* __restrict__ fc_w, const float* __restrict__ fc_b,
    float* __restrict__ out)
{
    extern __shared__ float sm[];
    u32*   A0   = (u32*)(sm + OF_A0);
    u32*   A1   = (u32*)(sm + OF_A1);
    float* xs   = sm + OF_XS;
    float* hfin = sm + OF_HFIN;

    const int tid  = threadIdx.x;
    const int lane = tid & 31;
    const int w    = tid >> 5;          // 16 warps
    const int g    = lane >> 2;         // row-quad / B-frag column
    const int tg   = lane & 3;          // accumulator column pair
    const int b0g  = blockIdx.x * 16;

    // ---------------- one-time staging ----------------
    for (int e = tid; e < 2048; e += NTHR) sm[e] = 0.f;   // zero A0+A1 (h(-1)=0)

    // stage ALL x: xs[t][b], lanes sweep t -> coalesced per b-row
    for (int e = tid; e < 16 * SS; e += NTHR) {
        int tc = e & (SS - 1), b = e >> 9;
        xs[tc * 16 + b] = x[(size_t)(b0g + b) * SS + tc];
    }

    // Gate-aligned column mapping:
    //   warp w, ntile t, col position p(0..7): unit = 4w + (p>>1), gate = 2t + (p&1)
    //   B-frag: this thread supplies col p = g  -> unit 4w + (g>>1), gate 2t + (g&1)
    //   C-frag: this thread owns cols 2tg,2tg+1 -> unit 4w + tg, gates (2t, 2t+1)
    u32 rh0[2][4][2], rh2[2][4][2], rh1[2][4][2];
#pragma unroll
    for (int nt = 0; nt < 2; nt++) {
        const int ub = 4 * w + (g >> 1);
        const int gr = (2 * nt + (g & 1)) * 64 + ub;     // weight row
#pragma unroll
        for (int kt = 0; kt < 4; kt++) {
            const int k0 = 16 * kt + 2 * tg;
            rh0[nt][kt][0] = pkh(w_hh0[gr * 64 + k0],     w_hh0[gr * 64 + k0 + 1]);
            rh0[nt][kt][1] = pkh(w_hh0[gr * 64 + k0 + 8], w_hh0[gr * 64 + k0 + 9]);
            rh2[nt][kt][0] = pkh(w_hh1[gr * 64 + k0],     w_hh1[gr * 64 + k0 + 1]);
            rh2[nt][kt][1] = pkh(w_hh1[gr * 64 + k0 + 8], w_hh1[gr * 64 + k0 + 9]);
            rh1[nt][kt][0] = pkh(w_ih1[gr * 64 + k0],     w_ih1[gr * 64 + k0 + 1]);
            rh1[nt][kt][1] = pkh(w_ih1[gr * 64 + k0 + 8], w_ih1[gr * 64 + k0 + 9]);
        }
    }

    // per-thread bias / input-weight registers (unit U = 4w + tg)
    const int U = 4 * w + tg;
    float b0r[2][2], b1r[2][2], wir[2][2];
#pragma unroll
    for (int nt = 0; nt < 2; nt++) {
#pragma unroll
        for (int q = 0; q < 2; q++) {
            const int gr = (2 * nt + q) * 64 + U;
            b0r[nt][q] = b_ih0[gr] + b_hh0[gr];
            b1r[nt][q] = b_ih1[gr] + b_hh1[gr];
            wir[nt][q] = w_ih0[gr];            // INPUT_SIZE == 1
        }
    }

    // publish byte offsets for h[row g][U] and h[row g+8][U] in the A-frag layout
    const int kt_  = U >> 4;
    const int kp8  = (U >> 1) & 7;
    const int wrd0 = (kt_ * 32 + (g * 4 + (kp8 & 3))) * 4 + (kp8 >= 4 ? 2 : 0);
    const int by0  = wrd0 * 4 + (U & 1) * 2;            // row g
    const int by1  = (wrd0 + 1) * 4 + (U & 1) * 2;      // row g+8

    float c0[2] = {0.f, 0.f}, c1[2] = {0.f, 0.f};
    float hv1[2] = {0.f, 0.f};
    __syncthreads();

    // ---------- recurrence: iteration k computes h0[k] and h1[k-1] ----------
    for (int k = 0; k <= SS; k++) {
        const u32* A0r = A0 + ((k + 1) & 1) * 512;   // h0[k-1]
        u32*       A0w = A0 + (k & 1) * 512;         // h0[k]
        const u32* A1r = A1 + (k & 1) * 512;         // h1[k-2]
        u32*       A1w = A1 + ((k + 1) & 1) * 512;   // h1[k-1]

        const float xg  = xs[(k & (SS - 1)) * 16 + g];
        const float xg8 = xs[(k & (SS - 1)) * 16 + g + 8];

        // ---- D0 = b0 + wih0*x[k] ;  D1a = b1 ;  D1b = 0 ----
        float D0[2][4], D1a[2][4], D1b[2][4];
#pragma unroll
        for (int nt = 0; nt < 2; nt++) {
            D0[nt][0] = fmaf(wir[nt][0], xg,  b0r[nt][0]);
            D0[nt][1] = fmaf(wir[nt][1], xg,  b0r[nt][1]);
            D0[nt][2] = fmaf(wir[nt][0], xg8, b0r[nt][0]);
            D0[nt][3] = fmaf(wir[nt][1], xg8, b0r[nt][1]);
            D1a[nt][0] = b1r[nt][0]; D1a[nt][1] = b1r[nt][1];
            D1a[nt][2] = b1r[nt][0]; D1a[nt][3] = b1r[nt][1];
            D1b[nt][0] = 0.f; D1b[nt][1] = 0.f;
            D1b[nt][2] = 0.f; D1b[nt][3] = 0.f;
        }

        // ---- 24 mma, three independent accumulator chains ----
#pragma unroll
        for (int kt = 0; kt < 4; kt++) {
            u32 a[4], b[4];
            *(uint4*)a = *(const uint4*)(A0r + (kt * 32 + lane) * 4);
            *(uint4*)b = *(const uint4*)(A1r + (kt * 32 + lane) * 4);
#pragma unroll
            for (int nt = 0; nt < 2; nt++) {
                mma16(D0[nt],  a, rh0[nt][kt][0], rh0[nt][kt][1]);
                mma16(D1a[nt], b, rh2[nt][kt][0], rh2[nt][kt][1]);
                mma16(D1b[nt], a, rh1[nt][kt][0], rh1[nt][kt][1]);
            }
        }

        // ---- cell 0 -> h0[k]  (fully thread-local: i,f in D0[0], g,o in D0[1]) ----
        if (k < SS) {
            // row g
            float cc = fmaf(sig_t(D0[0][1]), c0[0], sig_t(D0[0][0]) * tanhax(D0[1][0]));
            c0[0] = cc;
            *(unsigned short*)((char*)A0w + by0) = h16(sig_t(D0[1][1]) * tanhax(cc));
            // row g+8
            cc = fmaf(sig_t(D0[0][3]), c0[1], sig_t(D0[0][2]) * tanhax(D0[1][2]));
            c0[1] = cc;
            *(unsigned short*)((char*)A0w + by1) = h16(sig_t(D0[1][3]) * tanhax(cc));
        }

        // ---- cell 1 -> h1[k-1] ----
        if (k >= 1) {
            float m0 = D1a[0][0] + D1b[0][0];   // i  row g
            float m1 = D1a[0][1] + D1b[0][1];   // f
            float m2 = D1a[1][0] + D1b[1][0];   // g
            float m3 = D1a[1][1] + D1b[1][1];   // o
            float cc = fmaf(sig_t(m1), c1[0], sig_t(m0) * tanhax(m2));
            c1[0] = cc;
            hv1[0] = sig_t(m3) * tanhax(cc);
            *(unsigned short*)((char*)A1w + by0) = h16(hv1[0]);

            m0 = D1a[0][2] + D1b[0][2];         // i  row g+8
            m1 = D1a[0][3] + D1b[0][3];
            m2 = D1a[1][2] + D1b[1][2];
            m3 = D1a[1][3] + D1b[1][3];
            cc = fmaf(sig_t(m1), c1[1], sig_t(m0) * tanhax(m2));
            c1[1] = cc;
            hv1[1] = sig_t(m3) * tanhax(cc);
            *(unsigned short*)((char*)A1w + by1) = h16(hv1[1]);
        }
        __syncthreads();     // single barrier: all slot hazards separated here
    }

    // ---------------- epilogue (hv1 = h1[SS-1], full fp32) ----------------
    hfin[g * 64 + U]       = hv1[0];
    hfin[(g + 8) * 64 + U] = hv1[1];
    __syncthreads();

    for (int idx = tid; idx < 16 * OUTN; idx += NTHR) {
        int b = idx / OUTN, o = idx - b * OUTN;
        float s = fc_b[o];
#pragma unroll 16
        for (int uu = 0; uu < 64; uu++)
            s += hfin[b * 64 + uu] * fc_w[o * 64 + uu];
        out[(size_t)(b0g + b) * OUTN + o] = s;
    }
}

extern "C" void kernel_launch(void* const* d_in, const int* in_sizes, int n_in,
                              void* d_out, int out_size) {
    (void)in_sizes; (void)n_in; (void)out_size;
    const float* x     = (const float*)d_in[0];
    const float* w_ih0 = (const float*)d_in[1];
    const float* w_hh0 = (const float*)d_in[2];
    const float* b_ih0 = (const float*)d_in[3];
    const float* b_hh0 = (const float*)d_in[4];
    const float* w_ih1 = (const float*)d_in[5];
    const float* w_hh1 = (const float*)d_in[6];
    const float* b_ih1 = (const float*)d_in[7];
    const float* b_hh1 = (const float*)d_in[8];
    const float* fc_w  = (const float*)d_in[9];
    const float* fc_b  = (const float*)d_in[10];

    size_t smem = (size_t)SMEMF * sizeof(float);
    cudaFuncSetAttribute(lstm2_ga, cudaFuncAttributeMaxDynamicSharedMemorySize, (int)smem);
    lstm2_ga<<<CTAS, NTHR, smem>>>(x, w_ih0, w_hh0, b_ih0, b_hh0,
                                   w_ih1, w_hh1, b_ih1, b_hh1,
                                   fc_w, fc_b, (float*)d_out);
}